// round 2
// baseline (speedup 1.0000x reference)
#include <cuda_runtime.h>
#include <cuda_fp16.h>
#include <mma.h>

using namespace nvcuda;

#define NB 32
#define NS 325
#define NL 192
#define ND 128
#define NH 8
#define NHT 16
#define NN (NB*NS)          // 10400
#define NPAD_QK 10464
#define NPAD_V  10416
#define G4 512
#define TPAD 336
#define MLDM 344
#define MROWS 384
#define NEGV (-1000000000.0f)
#define LOG2E 1.4426950408889634f

// ---------------- device scratch (static allocations only) ----------------
__device__ __half d_WT[NHT*ND*G4];        // Whh^T per head-type, [ht][128][512] fp16
__device__ float  d_bsum[NHT*G4];         // bih+bhh
__device__ float  d_wih[NHT*G4];          // input weight column
__device__ __half d_QK[NHT*NPAD_QK*ND];   // q (ht 0..7) / k (ht 8..15) last hidden
__device__ __half d_V[NH*NPAD_V*NL];      // v LSTM full outputs
__device__ float  d_mask[MROWS*MLDM];     // precomputed additive mask

// ---------------- helpers ----------------
__device__ __forceinline__ float fast_sigmoid(float z){
    float e;
    asm("ex2.approx.f32 %0, %1;" : "=f"(e) : "f"(-LOG2E * z));
    float r;
    asm("rcp.approx.f32 %0, %1;" : "=f"(r) : "f"(1.0f + e));
    return r;
}
__device__ __forceinline__ float fast_tanh(float z){
    return fmaf(2.0f, fast_sigmoid(2.0f * z), -1.0f);
}
__device__ __forceinline__ float fast_exp(float z){
    float e;
    asm("ex2.approx.f32 %0, %1;" : "=f"(e) : "f"(LOG2E * z));
    return e;
}

// ---------------- prep kernels ----------------
__global__ void prep_weights(const float* qWih, const float* qWhh, const float* qbih, const float* qbhh,
                             const float* kWih, const float* kWhh, const float* kbih, const float* kbhh){
    int idx = blockIdx.x * blockDim.x + threadIdx.x;
    if (idx < NHT*ND*G4){
        int ht = idx / (ND*G4);
        int kk = (idx / G4) % ND;
        int r  = idx % G4;
        const float* W = (ht < NH) ? qWhh : kWhh;
        int h = ht & 7;
        d_WT[idx] = __float2half(W[(h*G4 + r)*ND + kk]);
    }
    if (idx < NHT*G4){
        int ht = idx / G4, r = idx % G4, h = ht & 7;
        if (ht < NH){
            d_bsum[idx] = qbih[h*G4+r] + qbhh[h*G4+r];
            d_wih[idx]  = qWih[h*G4+r];
        } else {
            d_bsum[idx] = kbih[h*G4+r] + kbhh[h*G4+r];
            d_wih[idx]  = kWih[h*G4+r];
        }
    }
}

__global__ void prep_mask(const float* graph){
    int idx = blockIdx.x * blockDim.x + threadIdx.x;
    if (idx < MROWS*MLDM){
        int s = idx / MLDM, t = idx % MLDM;
        float m = NEGV;
        if (s < NS && t < NS){
            if (s == t || graph[t*NS + s] != 0.0f) m = 0.0f;
        }
        d_mask[idx] = m;
    }
}

__global__ void zero_pads(){
    int idx = blockIdx.x * blockDim.x + threadIdx.x;
    const int qk_per = (NPAD_QK - NN) * ND;    // 64*128
    if (idx < NHT * qk_per){
        int ht = idx / qk_per, rem = idx % qk_per;
        d_QK[(size_t)ht*NPAD_QK*ND + (size_t)NN*ND + rem] = __float2half(0.0f);
    }
    const int v_per = (NPAD_V - NN) * NL;      // 16*192
    if (idx < NH * v_per){
        int h = idx / v_per, rem = idx % v_per;
        d_V[(size_t)h*NPAD_V*NL + (size_t)NN*NL + rem] = __float2half(0.0f);
    }
}

// ---------------- q/k LSTM: persistent block, weights in register fragments ----------------
// block = (head-type ht, tile of 16 sequences). 256 threads = 8 warps.
// Each warp owns 64 gate columns (4 wmma n-tiles); B fragments (Whh^T) live in registers.
__global__ void __launch_bounds__(256, 1) lstm_qk(const float* __restrict__ x){
    const int ht = blockIdx.y;
    const int n0 = blockIdx.x * 16;
    extern __shared__ char smem[];
    float*  z_s = (float*)smem;                              // [16][520] fp32
    __half* h_s = (__half*)(smem + 16*520*4);                // [16][136] fp16
    float*  x_s = (float*)(smem + 16*520*4 + 16*136*2);      // [16][192] fp32
    const int tid = threadIdx.x;
    const int wid = tid >> 5;

    // preload inputs for these 16 sequences (fully coalesced: x is [n][192] contiguous)
    for (int i = tid; i < 16*NL; i += 256)
        x_s[i] = x[(size_t)n0*NL + i];
    // zero initial hidden
    for (int i = tid; i < 16*136; i += 256)
        h_s[i] = __float2half(0.0f);

    // preload Whh^T fragments: warp wid -> n cols [wid*64, wid*64+64), all 8 k-tiles
    wmma::fragment<wmma::matrix_b, 16, 16, 16, __half, wmma::row_major> fb[4][8];
    const __half* WTbase = d_WT + (size_t)ht*ND*G4;
    #pragma unroll
    for (int nt = 0; nt < 4; nt++)
        #pragma unroll
        for (int kt = 0; kt < 8; kt++)
            wmma::load_matrix_sync(fb[nt][kt], WTbase + kt*16*G4 + wid*64 + nt*16, G4);

    // per-thread elementwise constants: thread owns unit u for 8 sequence rows
    const int u  = tid & 127;
    const int mh = tid >> 7;          // 0/1 -> rows [mh*8, mh*8+8)
    const float bi = d_bsum[ht*G4 + u];
    const float bf = d_bsum[ht*G4 + 128 + u];
    const float bg = d_bsum[ht*G4 + 256 + u];
    const float bo = d_bsum[ht*G4 + 384 + u];
    const float wi = d_wih[ht*G4 + u];
    const float wf = d_wih[ht*G4 + 128 + u];
    const float wg = d_wih[ht*G4 + 256 + u];
    const float wo = d_wih[ht*G4 + 384 + u];
    float c[8];
    #pragma unroll
    for (int j = 0; j < 8; j++) c[j] = 0.0f;

    __syncthreads();

    for (int t = 0; t < NL; t++){
        // Z[16,512] = H[16,128] @ Whh^T[128,512]
        wmma::fragment<wmma::accumulator, 16, 16, 16, float> fc[4];
        #pragma unroll
        for (int nt = 0; nt < 4; nt++) wmma::fill_fragment(fc[nt], 0.0f);
        #pragma unroll
        for (int kt = 0; kt < 8; kt++){
            wmma::fragment<wmma::matrix_a, 16, 16, 16, __half, wmma::row_major> fa;
            wmma::load_matrix_sync(fa, h_s + kt*16, 136);
            #pragma unroll
            for (int nt = 0; nt < 4; nt++)
                wmma::mma_sync(fc[nt], fa, fb[nt][kt], fc[nt]);
        }
        #pragma unroll
        for (int nt = 0; nt < 4; nt++)
            wmma::store_matrix_sync(z_s + wid*64 + nt*16, fc[nt], 520, wmma::mem_row_major);
        __syncthreads();

        // gate nonlinearities + state update (PyTorch gate order i,f,g,o)
        #pragma unroll
        for (int j = 0; j < 8; j++){
            int m = mh*8 + j;
            float xv = x_s[m*NL + t];
            float zi = z_s[m*520 +       u] + fmaf(xv, wi, bi);
            float zf = z_s[m*520 + 128 + u] + fmaf(xv, wf, bf);
            float zg = z_s[m*520 + 256 + u] + fmaf(xv, wg, bg);
            float zo = z_s[m*520 + 384 + u] + fmaf(xv, wo, bo);
            float ig = fast_sigmoid(zi);
            float fg = fast_sigmoid(zf);
            float gg = fast_tanh(zg);
            float og = fast_sigmoid(zo);
            float cn = fmaf(fg, c[j], ig * gg);
            c[j] = cn;
            float hn = og * fast_tanh(cn);
            h_s[m*136 + u] = __float2half(hn);
        }
        __syncthreads();
    }

    // write final hidden as q/k vectors
    for (int i = tid; i < 16*ND; i += 256){
        int m = i >> 7, uu = i & 127;
        d_QK[((size_t)ht*NPAD_QK + n0 + m)*ND + uu] = h_s[m*136 + uu];
    }
}

// ---------------- v LSTM (hidden size 1, scalar recurrence) ----------------
__global__ void lstm_v(const float* __restrict__ x,
                       const float* __restrict__ vWih, const float* __restrict__ vWhh,
                       const float* __restrict__ vbih, const float* __restrict__ vbhh){
    int g = blockIdx.x * blockDim.x + threadIdx.x;
    if (g >= NH * NN) return;
    int h = g / NN, n = g % NN;
    float wii = vWih[h*4+0], wif = vWih[h*4+1], wig = vWih[h*4+2], wio = vWih[h*4+3];
    float whi = vWhh[h*4+0], whf = vWhh[h*4+1], whg = vWhh[h*4+2], who = vWhh[h*4+3];
    float bi = vbih[h*4+0] + vbhh[h*4+0];
    float bf = vbih[h*4+1] + vbhh[h*4+1];
    float bg = vbih[h*4+2] + vbhh[h*4+2];
    float bo = vbih[h*4+3] + vbhh[h*4+3];
    const float* xr = x + (size_t)n*NL;
    __half* vout = d_V + ((size_t)h*NPAD_V + n)*NL;
    float hh = 0.0f, c = 0.0f;
    for (int t = 0; t < NL; t++){
        float xv = xr[t];
        float zi = fmaf(xv, wii, fmaf(hh, whi, bi));
        float zf = fmaf(xv, wif, fmaf(hh, whf, bf));
        float zg = fmaf(xv, wig, fmaf(hh, whg, bg));
        float zo = fmaf(xv, wio, fmaf(hh, who, bo));
        c = fmaf(fast_sigmoid(zf), c, fast_sigmoid(zi) * fast_tanh(zg));
        hh = fast_sigmoid(zo) * fast_tanh(c);
        vout[t] = __float2half(hh);
    }
}

// ---------------- attention: per (h, b, 64-row q-tile) ----------------
__global__ void __launch_bounds__(256, 1) attn_kernel(float* __restrict__ out){
    const int qt = blockIdx.x;   // 0..5
    const int b  = blockIdx.y;   // 0..31
    const int h  = blockIdx.z;   // 0..7
    extern __shared__ char smem[];
    float*  sc = (float*)smem;                                   // [64][344] fp32 scores
    __half* pa = (__half*)(smem + 64*MLDM*4);                    // [64][344] fp16 probs (unnormalized)
    float*  os = (float*)(smem + 64*MLDM*4 + 64*MLDM*2);         // [64][200] fp32 out staging
    float*  rs = (float*)(smem + 64*MLDM*4 + 64*MLDM*2 + 64*200*4); // [64] reciprocal row sums
    const int tid = threadIdx.x, wid = tid >> 5;
    const int s0 = qt * 64;
    const __half* Q = d_QK + ((size_t)h*NPAD_QK      + b*NS + s0) * ND;
    const __half* K = d_QK + ((size_t)(8+h)*NPAD_QK  + b*NS) * ND;
    const __half* V = d_V  + ((size_t)h*NPAD_V       + b*NS) * NL;

    // phase 1: scores = Q K^T
    for (int nt = wid; nt < 21; nt += 8){
        wmma::fragment<wmma::accumulator, 16, 16, 16, float> acc[4];
        #pragma unroll
        for (int mt = 0; mt < 4; mt++) wmma::fill_fragment(acc[mt], 0.0f);
        #pragma unroll
        for (int kt = 0; kt < 8; kt++){
            wmma::fragment<wmma::matrix_b, 16, 16, 16, __half, wmma::col_major> fbk;
            wmma::load_matrix_sync(fbk, K + nt*16*ND + kt*16, ND);
            #pragma unroll
            for (int mt = 0; mt < 4; mt++){
                wmma::fragment<wmma::matrix_a, 16, 16, 16, __half, wmma::row_major> fa;
                wmma::load_matrix_sync(fa, Q + mt*16*ND + kt*16, ND);
                wmma::mma_sync(acc[mt], fa, fbk, acc[mt]);
            }
        }
        #pragma unroll
        for (int mt = 0; mt < 4; mt++)
            wmma::store_matrix_sync(sc + mt*16*MLDM + nt*16, acc[mt], MLDM, wmma::mem_row_major);
    }
    __syncthreads();

    // phase 2: scale, leaky, mask, softmax (4 threads per row)
    {
        const int r  = tid >> 2;
        const int q4 = tid & 3;
        const float* mrow = d_mask + (s0 + r) * MLDM;
        float* srow = sc + r * MLDM;
        const float scale = 0.08838834764831845f; // 1/sqrt(128)
        float mx = -3.4e38f;
        for (int t = q4; t < TPAD; t += 4){
            float v = srow[t] * scale;
            v = (v >= 0.0f) ? v : 0.2f * v;
            v += mrow[t];
            srow[t] = v;
            mx = fmaxf(mx, v);
        }
        mx = fmaxf(mx, __shfl_xor_sync(0xffffffffu, mx, 1));
        mx = fmaxf(mx, __shfl_xor_sync(0xffffffffu, mx, 2));
        float sum = 0.0f;
        __half* prow = pa + r * MLDM;
        for (int t = q4; t < TPAD; t += 4){
            float e = fast_exp(srow[t] - mx);
            sum += e;
            prow[t] = __float2half(e);
        }
        sum += __shfl_xor_sync(0xffffffffu, sum, 1);
        sum += __shfl_xor_sync(0xffffffffu, sum, 2);
        if (q4 == 0) rs[r] = 1.0f / sum;
    }
    __syncthreads();

    // phase 3: out = probs @ V
    for (int nt = wid; nt < 12; nt += 8){
        wmma::fragment<wmma::accumulator, 16, 16, 16, float> acc[4];
        #pragma unroll
        for (int mt = 0; mt < 4; mt++) wmma::fill_fragment(acc[mt], 0.0f);
        for (int kt = 0; kt < 21; kt++){
            wmma::fragment<wmma::matrix_b, 16, 16, 16, __half, wmma::row_major> fbv;
            wmma::load_matrix_sync(fbv, V + kt*16*NL + nt*16, NL);
            #pragma unroll
            for (int mt = 0; mt < 4; mt++){
                wmma::fragment<wmma::matrix_a, 16, 16, 16, __half, wmma::row_major> fa;
                wmma::load_matrix_sync(fa, pa + mt*16*MLDM + kt*16, MLDM);
                wmma::mma_sync(acc[mt], fa, fbv, acc[mt]);
            }
        }
        #pragma unroll
        for (int mt = 0; mt < 4; mt++)
            wmma::store_matrix_sync(os + mt*16*200 + nt*16, acc[mt], 200, wmma::mem_row_major);
    }
    __syncthreads();

    // epilogue: normalize, leaky, scatter to [B,S,L,H]
    for (int i = tid; i < 64*NL; i += 256){
        int m = i / NL, l = i % NL;
        int s = s0 + m;
        if (s < NS){
            float v = os[m*200 + l] * rs[m];
            v = (v >= 0.0f) ? v : 0.2f * v;
            out[(((size_t)b*NS + s)*NL + l)*NH + h] = v;
        }
    }
}

// ---------------- launch ----------------
extern "C" void kernel_launch(void* const* d_in, const int* in_sizes, int n_in,
                              void* d_out, int out_size){
    const float* x     = (const float*)d_in[0];
    const float* graph = (const float*)d_in[1];
    const float* qWih  = (const float*)d_in[2];
    const float* qWhh  = (const float*)d_in[3];
    const float* qbih  = (const float*)d_in[4];
    const float* qbhh  = (const float*)d_in[5];
    const float* kWih  = (const float*)d_in[6];
    const float* kWhh  = (const float*)d_in[7];
    const float* kbih  = (const float*)d_in[8];
    const float* kbhh  = (const float*)d_in[9];
    const float* vWih  = (const float*)d_in[10];
    const float* vWhh  = (const float*)d_in[11];
    const float* vbih  = (const float*)d_in[12];
    const float* vbhh  = (const float*)d_in[13];
    float* out = (float*)d_out;

    const int lstm_smem = 16*520*4 + 16*136*2 + 16*192*4;                       // 49920
    const int attn_smem = 64*MLDM*4 + 64*MLDM*2 + 64*200*4 + 64*4;              // 183808
    cudaFuncSetAttribute(lstm_qk,     cudaFuncAttributeMaxDynamicSharedMemorySize, lstm_smem);
    cudaFuncSetAttribute(attn_kernel, cudaFuncAttributeMaxDynamicSharedMemorySize, attn_smem);

    prep_weights<<<(NHT*ND*G4 + 255)/256, 256>>>(qWih, qWhh, qbih, qbhh, kWih, kWhh, kbih, kbhh);
    prep_mask<<<(MROWS*MLDM + 255)/256, 256>>>(graph);
    zero_pads<<<(NHT*(NPAD_QK-NN)*ND + 255)/256, 256>>>();

    lstm_qk<<<dim3(NN/16, NHT), 256, lstm_smem>>>(x);
    lstm_v<<<(NH*NN + 255)/256, 256>>>(x, vWih, vWhh, vbih, vbhh);
    attn_kernel<<<dim3(6, NB, NH), 256, attn_smem>>>(out);
}

// round 3
// speedup vs baseline: 1.4268x; 1.4268x over previous
#include <cuda_runtime.h>
#include <cuda_fp16.h>
#include <mma.h>

using namespace nvcuda;

#define NB 32
#define NS 325
#define NL 192
#define ND 128
#define NH 8
#define NHT 16
#define NN (NB*NS)          // 10400
#define NPAD_QK 10464
#define NPAD_V  10416
#define G4 512
#define TPAD 336
#define MLDM 344
#define MROWS 384
#define NEGV (-1000000000.0f)
#define LOG2E 1.4426950408889634f
#define ZLD 68
#define HLD 136

// ---------------- device scratch (static allocations only) ----------------
__device__ __half d_WT[NHT*ND*G4];        // Whh^T per head-type, gate-permuted cols, [ht][128][512] fp16
__device__ float  d_bsum[NHT*G4];         // bih+bhh (permuted)
__device__ float  d_wih[NHT*G4];          // input weight column (permuted)
__device__ __half d_QK[NHT*NPAD_QK*ND];   // q (ht 0..7) / k (ht 8..15) last hidden
__device__ __half d_V[NH*NPAD_V*NL];      // v LSTM full outputs
__device__ float  d_mask[MROWS*MLDM];     // precomputed additive mask

// ---------------- helpers ----------------
__device__ __forceinline__ float ftanh(float z){
    float r;
    asm("tanh.approx.f32 %0, %1;" : "=f"(r) : "f"(z));
    return r;
}
__device__ __forceinline__ float fsig(float z){
    return fmaf(0.5f, ftanh(0.5f * z), 0.5f);
}
__device__ __forceinline__ float fast_exp(float z){
    float e;
    asm("ex2.approx.f32 %0, %1;" : "=f"(e) : "f"(LOG2E * z));
    return e;
}

// ---------------- prep kernels ----------------
// Column permutation: permuted col pc = w*64 + gate*16 + li  <-> original row r0 = gate*128 + w*16 + li
__global__ void prep_weights(const float* qWih, const float* qWhh, const float* qbih, const float* qbhh,
                             const float* kWih, const float* kWhh, const float* kbih, const float* kbhh){
    int idx = blockIdx.x * blockDim.x + threadIdx.x;
    if (idx < NHT*ND*G4){
        int ht = idx / (ND*G4);
        int kk = (idx / G4) % ND;
        int pc = idx % G4;
        int w = pc >> 6, g = (pc >> 4) & 3, li = pc & 15;
        int r0 = g*128 + w*16 + li;
        const float* W = (ht < NH) ? qWhh : kWhh;
        int h = ht & 7;
        d_WT[idx] = __float2half(W[(h*G4 + r0)*ND + kk]);
    }
    if (idx < NHT*G4){
        int ht = idx / G4, pc = idx % G4, h = ht & 7;
        int w = pc >> 6, g = (pc >> 4) & 3, li = pc & 15;
        int r0 = g*128 + w*16 + li;
        if (ht < NH){
            d_bsum[idx] = qbih[h*G4+r0] + qbhh[h*G4+r0];
            d_wih[idx]  = qWih[h*G4+r0];
        } else {
            d_bsum[idx] = kbih[h*G4+r0] + kbhh[h*G4+r0];
            d_wih[idx]  = kWih[h*G4+r0];
        }
    }
}

__global__ void prep_mask(const float* graph){
    int idx = blockIdx.x * blockDim.x + threadIdx.x;
    if (idx < MROWS*MLDM){
        int s = idx / MLDM, t = idx % MLDM;
        float m = NEGV;
        if (s < NS && t < NS){
            if (s == t || graph[t*NS + s] != 0.0f) m = 0.0f;
        }
        d_mask[idx] = m;
    }
}

__global__ void zero_pads(){
    int idx = blockIdx.x * blockDim.x + threadIdx.x;
    const int qk_per = (NPAD_QK - NN) * ND;    // 64*128
    if (idx < NHT * qk_per){
        int ht = idx / qk_per, rem = idx % qk_per;
        d_QK[(size_t)ht*NPAD_QK*ND + (size_t)NN*ND + rem] = __float2half(0.0f);
    }
    const int v_per = (NPAD_V - NN) * NL;      // 16*192
    if (idx < NH * v_per){
        int h = idx / v_per, rem = idx % v_per;
        d_V[(size_t)h*NPAD_V*NL + (size_t)NN*NL + rem] = __float2half(0.0f);
    }
}

// ---------------- q/k LSTM ----------------
// block = (head-type ht, tile of 32 sequences split into 2 pipelined groups of 16).
// 256 threads = 8 warps; warp w's MMA output columns are gates i,f,g,o for units [w*16, w*16+16)
// (gate-permuted weights) -> z stays warp-private, elementwise overlaps the other group's MMA.

__device__ __forceinline__ void ew_step(int go, int tx, float* z_s, __half* h_s, const float* x_s,
                                        int wid, int lane, float* cst,
                                        float bi, float bf, float bg, float bo,
                                        float wi, float wf, float wg, float wo){
    const int li = lane & 15;
    const int rb = (lane >> 4) * 8;
    const float* zw = z_s + (wid*2 + go)*16*ZLD;
    __half* hb = h_s + go*16*HLD + wid*16 + li;
    const float* xb = x_s + (go*16 + rb)*NL + tx;
    #pragma unroll
    for (int j = 0; j < 8; j++){
        int r = rb + j;
        float xv = xb[j*NL];
        const float* zr = zw + r*ZLD + li;
        float zi = zr[0]  + fmaf(xv, wi, bi);
        float zf = zr[16] + fmaf(xv, wf, bf);
        float zg = zr[32] + fmaf(xv, wg, bg);
        float zo = zr[48] + fmaf(xv, wo, bo);
        float cn = fmaf(fsig(zf), cst[j], fsig(zi) * ftanh(zg));
        cst[j] = cn;
        hb[r*HLD] = __float2half(fsig(zo) * ftanh(cn));
    }
}

template<int G>
__device__ __forceinline__ void mma_group(const __half* h_s,
        wmma::fragment<wmma::matrix_b,16,16,16,__half,wmma::row_major> (&fb)[4][8],
        wmma::fragment<wmma::accumulator,16,16,16,float> (&fc)[4]){
    #pragma unroll
    for (int nt = 0; nt < 4; nt++) wmma::fill_fragment(fc[nt], 0.0f);
    const __half* hbase = h_s + G*16*HLD;
    #pragma unroll
    for (int kt = 0; kt < 8; kt++){
        wmma::fragment<wmma::matrix_a,16,16,16,__half,wmma::row_major> fa;
        wmma::load_matrix_sync(fa, hbase + kt*16, HLD);
        #pragma unroll
        for (int nt = 0; nt < 4; nt++)
            wmma::mma_sync(fc[nt], fa, fb[nt][kt], fc[nt]);
    }
}

template<int G>
__device__ __forceinline__ void store_group(float* z_s, int wid,
        wmma::fragment<wmma::accumulator,16,16,16,float> (&fc)[4]){
    float* zw = z_s + (wid*2 + G)*16*ZLD;
    #pragma unroll
    for (int nt = 0; nt < 4; nt++)
        wmma::store_matrix_sync(zw + nt*16, fc[nt], ZLD, wmma::mem_row_major);
}

__global__ void __launch_bounds__(256, 1) lstm_qk(const float* __restrict__ x){
    const int ht = blockIdx.y;
    const int n0 = blockIdx.x * 32;
    extern __shared__ char smem[];
    float*  z_s = (float*)smem;                                   // [8 warps][2 grp][16][ZLD]
    __half* h_s = (__half*)(smem + 8*2*16*ZLD*4);                 // [2 grp][16][HLD]
    float*  x_s = (float*)(smem + 8*2*16*ZLD*4 + 2*16*HLD*2);     // [32][NL]
    const int tid = threadIdx.x;
    const int wid = tid >> 5;
    const int lane = tid & 31;
    const int li = lane & 15;

    for (int i = tid; i < 32*NL; i += 256)
        x_s[i] = x[(size_t)n0*NL + i];
    for (int i = tid; i < 2*16*HLD; i += 256)
        h_s[i] = __float2half(0.0f);

    // weight-stationary B fragments (gate-permuted)
    wmma::fragment<wmma::matrix_b, 16, 16, 16, __half, wmma::row_major> fb[4][8];
    const __half* WTbase = d_WT + (size_t)ht*ND*G4;
    #pragma unroll
    for (int nt = 0; nt < 4; nt++)
        #pragma unroll
        for (int kt = 0; kt < 8; kt++)
            wmma::load_matrix_sync(fb[nt][kt], WTbase + kt*16*G4 + wid*64 + nt*16, G4);

    // per-lane gate constants for unit u = wid*16 + li (permuted layout)
    const int pb = ht*G4 + wid*64 + li;
    const float bi = d_bsum[pb],      bf = d_bsum[pb+16];
    const float bg = d_bsum[pb+32],   bo = d_bsum[pb+48];
    const float wi = d_wih[pb],       wf = d_wih[pb+16];
    const float wg = d_wih[pb+32],    wo = d_wih[pb+48];

    float cA[8], cB[8];
    #pragma unroll
    for (int j = 0; j < 8; j++){ cA[j] = 0.0f; cB[j] = 0.0f; }

    __syncthreads();

    wmma::fragment<wmma::accumulator, 16, 16, 16, float> fc[4];
    for (int t = 0; t < NL; t++){
        // phase 1: MMA group A at t; elementwise group B finishing step t-1
        mma_group<0>(h_s, fb, fc);
        if (t > 0) ew_step(1, t-1, z_s, h_s, x_s, wid, lane, cB, bi,bf,bg,bo, wi,wf,wg,wo);
        store_group<0>(z_s, wid, fc);
        __syncthreads();
        // phase 2: MMA group B at t; elementwise group A at t
        mma_group<1>(h_s, fb, fc);
        ew_step(0, t, z_s, h_s, x_s, wid, lane, cA, bi,bf,bg,bo, wi,wf,wg,wo);
        store_group<1>(z_s, wid, fc);
        __syncthreads();
    }
    // epilogue: finish group B's last step
    ew_step(1, NL-1, z_s, h_s, x_s, wid, lane, cB, bi,bf,bg,bo, wi,wf,wg,wo);
    __syncthreads();

    // write final hidden as q/k vectors (rows 0-15 = group A, 16-31 = group B)
    for (int i = tid; i < 32*ND; i += 256){
        int m = i >> 7, u = i & 127;
        d_QK[((size_t)ht*NPAD_QK + n0 + m)*ND + u] =
            h_s[(m >> 4)*16*HLD + (m & 15)*HLD + u];
    }
}

// ---------------- v LSTM (hidden size 1, scalar recurrence) ----------------
__global__ void lstm_v(const float* __restrict__ x,
                       const float* __restrict__ vWih, const float* __restrict__ vWhh,
                       const float* __restrict__ vbih, const float* __restrict__ vbhh){
    int g = blockIdx.x * blockDim.x + threadIdx.x;
    if (g >= NH * NN) return;
    int h = g / NN, n = g % NN;
    float wii = vWih[h*4+0], wif = vWih[h*4+1], wig = vWih[h*4+2], wio = vWih[h*4+3];
    float whi = vWhh[h*4+0], whf = vWhh[h*4+1], whg = vWhh[h*4+2], who = vWhh[h*4+3];
    float bi = vbih[h*4+0] + vbhh[h*4+0];
    float bf = vbih[h*4+1] + vbhh[h*4+1];
    float bg = vbih[h*4+2] + vbhh[h*4+2];
    float bo = vbih[h*4+3] + vbhh[h*4+3];
    const float* xr = x + (size_t)n*NL;
    __half* vout = d_V + ((size_t)h*NPAD_V + n)*NL;
    float hh = 0.0f, c = 0.0f;
    for (int t = 0; t < NL; t++){
        float xv = xr[t];
        float zi = fmaf(xv, wii, fmaf(hh, whi, bi));
        float zf = fmaf(xv, wif, fmaf(hh, whf, bf));
        float zg = fmaf(xv, wig, fmaf(hh, whg, bg));
        float zo = fmaf(xv, wio, fmaf(hh, who, bo));
        c = fmaf(fsig(zf), c, fsig(zi) * ftanh(zg));
        hh = fsig(zo) * ftanh(c);
        vout[t] = __float2half(hh);
    }
}

// ---------------- attention: per (h, b, 64-row q-tile) ----------------
__global__ void __launch_bounds__(256, 1) attn_kernel(float* __restrict__ out){
    const int qt = blockIdx.x;   // 0..5
    const int b  = blockIdx.y;   // 0..31
    const int h  = blockIdx.z;   // 0..7
    extern __shared__ char smem[];
    float*  sc = (float*)smem;                                   // [64][344] fp32 scores
    __half* pa = (__half*)(smem + 64*MLDM*4);                    // [64][344] fp16 probs (unnormalized)
    float*  os = (float*)(smem + 64*MLDM*4 + 64*MLDM*2);         // [64][200] fp32 out staging
    float*  rs = (float*)(smem + 64*MLDM*4 + 64*MLDM*2 + 64*200*4); // [64] reciprocal row sums
    const int tid = threadIdx.x, wid = tid >> 5;
    const int s0 = qt * 64;
    const __half* Q = d_QK + ((size_t)h*NPAD_QK      + b*NS + s0) * ND;
    const __half* K = d_QK + ((size_t)(8+h)*NPAD_QK  + b*NS) * ND;
    const __half* V = d_V  + ((size_t)h*NPAD_V       + b*NS) * NL;

    // phase 1: scores = Q K^T
    for (int nt = wid; nt < 21; nt += 8){
        wmma::fragment<wmma::accumulator, 16, 16, 16, float> acc[4];
        #pragma unroll
        for (int mt = 0; mt < 4; mt++) wmma::fill_fragment(acc[mt], 0.0f);
        #pragma unroll
        for (int kt = 0; kt < 8; kt++){
            wmma::fragment<wmma::matrix_b, 16, 16, 16, __half, wmma::col_major> fbk;
            wmma::load_matrix_sync(fbk, K + nt*16*ND + kt*16, ND);
            #pragma unroll
            for (int mt = 0; mt < 4; mt++){
                wmma::fragment<wmma::matrix_a, 16, 16, 16, __half, wmma::row_major> fa;
                wmma::load_matrix_sync(fa, Q + mt*16*ND + kt*16, ND);
                wmma::mma_sync(acc[mt], fa, fbk, acc[mt]);
            }
        }
        #pragma unroll
        for (int mt = 0; mt < 4; mt++)
            wmma::store_matrix_sync(sc + mt*16*MLDM + nt*16, acc[mt], MLDM, wmma::mem_row_major);
    }
    __syncthreads();

    // phase 2: scale, leaky, mask, softmax (4 threads per row)
    {
        const int r  = tid >> 2;
        const int q4 = tid & 3;
        const float* mrow = d_mask + (s0 + r) * MLDM;
        float* srow = sc + r * MLDM;
        const float scale = 0.08838834764831845f; // 1/sqrt(128)
        float mx = -3.4e38f;
        for (int t = q4; t < TPAD; t += 4){
            float v = srow[t] * scale;
            v = (v >= 0.0f) ? v : 0.2f * v;
            v += mrow[t];
            srow[t] = v;
            mx = fmaxf(mx, v);
        }
        mx = fmaxf(mx, __shfl_xor_sync(0xffffffffu, mx, 1));
        mx = fmaxf(mx, __shfl_xor_sync(0xffffffffu, mx, 2));
        float sum = 0.0f;
        __half* prow = pa + r * MLDM;
        for (int t = q4; t < TPAD; t += 4){
            float e = fast_exp(srow[t] - mx);
            sum += e;
            prow[t] = __float2half(e);
        }
        sum += __shfl_xor_sync(0xffffffffu, sum, 1);
        sum += __shfl_xor_sync(0xffffffffu, sum, 2);
        if (q4 == 0) rs[r] = 1.0f / sum;
    }
    __syncthreads();

    // phase 3: out = probs @ V
    for (int nt = wid; nt < 12; nt += 8){
        wmma::fragment<wmma::accumulator, 16, 16, 16, float> acc[4];
        #pragma unroll
        for (int mt = 0; mt < 4; mt++) wmma::fill_fragment(acc[mt], 0.0f);
        for (int kt = 0; kt < 21; kt++){
            wmma::fragment<wmma::matrix_b, 16, 16, 16, __half, wmma::row_major> fbv;
            wmma::load_matrix_sync(fbv, V + kt*16*NL + nt*16, NL);
            #pragma unroll
            for (int mt = 0; mt < 4; mt++){
                wmma::fragment<wmma::matrix_a, 16, 16, 16, __half, wmma::row_major> fa;
                wmma::load_matrix_sync(fa, pa + mt*16*MLDM + kt*16, MLDM);
                wmma::mma_sync(acc[mt], fa, fbv, acc[mt]);
            }
        }
        #pragma unroll
        for (int mt = 0; mt < 4; mt++)
            wmma::store_matrix_sync(os + mt*16*200 + nt*16, acc[mt], 200, wmma::mem_row_major);
    }
    __syncthreads();

    // epilogue: normalize, leaky, scatter to [B,S,L,H]
    for (int i = tid; i < 64*NL; i += 256){
        int m = i / NL, l = i % NL;
        int s = s0 + m;
        if (s < NS){
            float v = os[m*200 + l] * rs[m];
            v = (v >= 0.0f) ? v : 0.2f * v;
            out[(((size_t)b*NS + s)*NL + l)*NH + h] = v;
        }
    }
}

// ---------------- launch ----------------
extern "C" void kernel_launch(void* const* d_in, const int* in_sizes, int n_in,
                              void* d_out, int out_size){
    const float* x     = (const float*)d_in[0];
    const float* graph = (const float*)d_in[1];
    const float* qWih  = (const float*)d_in[2];
    const float* qWhh  = (const float*)d_in[3];
    const float* qbih  = (const float*)d_in[4];
    const float* qbhh  = (const float*)d_in[5];
    const float* kWih  = (const float*)d_in[6];
    const float* kWhh  = (const float*)d_in[7];
    const float* kbih  = (const float*)d_in[8];
    const float* kbhh  = (const float*)d_in[9];
    const float* vWih  = (const float*)d_in[10];
    const float* vWhh  = (const float*)d_in[11];
    const float* vbih  = (const float*)d_in[12];
    const float* vbhh  = (const float*)d_in[13];
    float* out = (float*)d_out;

    const int lstm_smem = 8*2*16*ZLD*4 + 2*16*HLD*2 + 32*NL*4;                  // 102912
    const int attn_smem = 64*MLDM*4 + 64*MLDM*2 + 64*200*4 + 64*4;              // 183808
    cudaFuncSetAttribute(lstm_qk,     cudaFuncAttributeMaxDynamicSharedMemorySize, lstm_smem);
    cudaFuncSetAttribute(attn_kernel, cudaFuncAttributeMaxDynamicSharedMemorySize, attn_smem);

    prep_weights<<<(NHT*ND*G4 + 255)/256, 256>>>(qWih, qWhh, qbih, qbhh, kWih, kWhh, kbih, kbhh);
    prep_mask<<<(MROWS*MLDM + 255)/256, 256>>>(graph);
    zero_pads<<<(NHT*(NPAD_QK-NN)*ND + 255)/256, 256>>>();

    lstm_qk<<<dim3(NN/32, NHT), 256, lstm_smem>>>(x);
    lstm_v<<<(NH*NN + 255)/256, 256>>>(x, vWih, vWhh, vbih, vbhh);
    attn_kernel<<<dim3(6, NB, NH), 256, attn_smem>>>(out);
}

// round 4
// speedup vs baseline: 2.2121x; 1.5503x over previous
#include <cuda_runtime.h>
#include <cuda_fp16.h>
#include <cstdint>
#include <mma.h>

using namespace nvcuda;

#define NB 32
#define NS 325
#define NL 192
#define ND 128
#define NH 8
#define NHT 16
#define NN (NB*NS)          // 10400
#define NPAD_QK 10464
#define NPAD_V  10416
#define G4 512
#define TPAD 336
#define MLDM 344
#define MROWS 384
#define NEGV (-1000000000.0f)
#define LOG2E 1.4426950408889634f
#define HLD 152             // h_aug row stride in halves (cols 0-127 h, 128=1, 129=x, 130-151 pad0)
#define WB_TOT (16*8*9*8*32)

// ---------------- device scratch (static allocations only) ----------------
__device__ uint2  d_WB[WB_TOT];           // pre-swizzled B fragments [ht][warp][kt 0..8][j][lane]
__device__ __half d_QK[NHT*NPAD_QK*ND];   // q (ht 0..7) / k (ht 8..15) last hidden
__device__ __half d_V[NH*NPAD_V*NL];      // v LSTM full outputs
__device__ float  d_mask[MROWS*MLDM];     // precomputed additive mask

// ---------------- helpers ----------------
__device__ __forceinline__ float ftanh(float z){
    float r;
    asm("tanh.approx.f32 %0, %1;" : "=f"(r) : "f"(z));
    return r;
}
__device__ __forceinline__ float fsig(float z){
    return fmaf(0.5f, ftanh(0.5f * z), 0.5f);
}
__device__ __forceinline__ float fast_exp(float z){
    float e;
    asm("ex2.approx.f32 %0, %1;" : "=f"(e) : "f"(LOG2E * z));
    return e;
}
__device__ __forceinline__ void ldm4(uint32_t (&a)[4], uint32_t addr){
    asm volatile("ldmatrix.sync.aligned.m8n8.x4.shared.b16 {%0,%1,%2,%3}, [%4];"
        : "=r"(a[0]), "=r"(a[1]), "=r"(a[2]), "=r"(a[3]) : "r"(addr));
}
__device__ __forceinline__ void mma16816(float (&c)[4], const uint32_t (&a)[4], uint2 b){
    asm volatile("mma.sync.aligned.m16n8k16.row.col.f32.f16.f16.f32 "
        "{%0,%1,%2,%3}, {%4,%5,%6,%7}, {%8,%9}, {%0,%1,%2,%3};"
        : "+f"(c[0]), "+f"(c[1]), "+f"(c[2]), "+f"(c[3])
        : "r"(a[0]), "r"(a[1]), "r"(a[2]), "r"(a[3]), "r"(b.x), "r"(b.y));
}

// ---------------- prep: build pre-swizzled B fragments ----------------
// Column permutation within a warp's 64 output cols: col c = 32*hb + 8*g + 2*q + e
// maps to (gate g, unit u' = q*4 + hb*2 + e). Augmented k: row128=bias, row129=wih.
__global__ void prep_wb(const float* qWih, const float* qWhh, const float* qbih, const float* qbhh,
                        const float* kWih, const float* kWhh, const float* kbih, const float* kbhh){
    int idx = blockIdx.x * blockDim.x + threadIdx.x;
    if (idx >= WB_TOT) return;
    int l  = idx & 31;
    int j  = (idx >> 5) & 7;
    int kt = (idx >> 8) % 9;
    int rest = idx / 2304;
    int w  = rest & 7;
    int ht = rest >> 3;
    const float* Wih = (ht < NH) ? qWih : kWih;
    const float* Whh = (ht < NH) ? qWhh : kWhh;
    const float* bih = (ht < NH) ? qbih : kbih;
    const float* bhh = (ht < NH) ? qbhh : kbhh;
    int h = ht & 7;
    int p = l >> 2, qk = l & 3;
    int hb = j >> 2, g = j & 3;
    int u  = (p >> 1)*4 + hb*2 + (p & 1);
    int r0 = g*128 + w*16 + u;

    float ev[4];
    int kb = kt*16 + qk*2;
    int kk[4] = {kb, kb+1, kb+8, kb+9};
    #pragma unroll
    for (int i = 0; i < 4; i++){
        int k = kk[i];
        float v = 0.0f;
        if (k < 128)        v = Whh[(h*G4 + r0)*ND + k];
        else if (k == 128)  v = bih[h*G4 + r0] + bhh[h*G4 + r0];
        else if (k == 129)  v = Wih[h*G4 + r0];
        ev[i] = v;
    }
    __half2 b0 = __floats2half2_rn(ev[0], ev[1]);
    __half2 b1 = __floats2half2_rn(ev[2], ev[3]);
    uint2 out;
    out.x = *reinterpret_cast<unsigned*>(&b0);
    out.y = *reinterpret_cast<unsigned*>(&b1);
    d_WB[idx] = out;
}

__global__ void prep_mask(const float* graph){
    int idx = blockIdx.x * blockDim.x + threadIdx.x;
    if (idx < MROWS*MLDM){
        int s = idx / MLDM, t = idx % MLDM;
        float m = NEGV;
        if (s < NS && t < NS){
            if (s == t || graph[t*NS + s] != 0.0f) m = 0.0f;
        }
        d_mask[idx] = m;
    }
}

__global__ void zero_pads(){
    int idx = blockIdx.x * blockDim.x + threadIdx.x;
    const int qk_per = (NPAD_QK - NN) * ND;    // 64*128
    if (idx < NHT * qk_per){
        int ht = idx / qk_per, rem = idx % qk_per;
        d_QK[(size_t)ht*NPAD_QK*ND + (size_t)NN*ND + rem] = __float2half(0.0f);
    }
    const int v_per = (NPAD_V - NN) * NL;      // 16*192
    if (idx < NH * v_per){
        int h = idx / v_per, rem = idx % v_per;
        d_V[(size_t)h*NPAD_V*NL + (size_t)NN*NL + rem] = __float2half(0.0f);
    }
}

// ---------------- q/k LSTM: register-resident gates via raw mma.sync ----------------
__device__ __forceinline__ void mma_group(uint32_t abase, const uint2 (&fbw)[9][8], float (&acc)[8][4]){
    #pragma unroll
    for (int j = 0; j < 8; j++)
        #pragma unroll
        for (int r = 0; r < 4; r++) acc[j][r] = 0.0f;
    uint32_t a[4], an[4];
    ldm4(a, abase);
    #pragma unroll
    for (int kt = 0; kt < 9; kt++){
        if (kt < 8) ldm4(an, abase + (kt+1)*32);
        #pragma unroll
        for (int j = 0; j < 8; j++) mma16816(acc[j], a, fbw[kt][j]);
        #pragma unroll
        for (int r = 0; r < 4; r++) a[r] = an[r];
    }
}

__device__ __forceinline__ void ew_step(float (&acc)[8][4], float (&cst)[2][4], __half* hg,
                                        const float* x_s, int rowbase, int t, int wid, int lane){
    const int q = lane & 3, p = lane >> 2;
    #pragma unroll
    for (int rs = 0; rs < 2; rs++){
        float hv[4];
        #pragma unroll
        for (int hb = 0; hb < 2; hb++)
            #pragma unroll
            for (int e = 0; e < 2; e++){
                int ci = 2*rs + e;
                float zi = acc[4*hb + 0][ci];
                float zf = acc[4*hb + 1][ci];
                float zg = acc[4*hb + 2][ci];
                float zo = acc[4*hb + 3][ci];
                float cn = fmaf(fsig(zf), cst[rs][hb*2+e], fsig(zi) * ftanh(zg));
                cst[rs][hb*2+e] = cn;
                hv[hb*2+e] = fsig(zo) * ftanh(cn);
            }
        int row = p + 8*rs;
        __half2 h01 = __floats2half2_rn(hv[0], hv[1]);
        __half2 h23 = __floats2half2_rn(hv[2], hv[3]);
        uint2 pk;
        pk.x = *reinterpret_cast<unsigned*>(&h01);
        pk.y = *reinterpret_cast<unsigned*>(&h23);
        *reinterpret_cast<uint2*>(hg + row*HLD + wid*16 + q*4) = pk;
    }
    // refresh the x lane (col 129) for this group's next step (one warp does it)
    if (wid == 0 && q == 0 && t + 1 < NL){
        hg[p*HLD + 129]     = __float2half(x_s[(rowbase + p)*NL + t + 1]);
        hg[(p+8)*HLD + 129] = __float2half(x_s[(rowbase + p + 8)*NL + t + 1]);
    }
}

__global__ void __launch_bounds__(256, 1) lstm_qk(const float* __restrict__ x){
    const int ht = blockIdx.y;
    const int n0 = blockIdx.x * 32;
    extern __shared__ char smem[];
    __half* h_s = (__half*)smem;                       // [2][16][HLD] augmented h
    float*  x_s = (float*)(smem + 2*16*HLD*2);         // [32][NL]
    const int tid = threadIdx.x;
    const int wid = tid >> 5;
    const int lane = tid & 31;

    for (int i = tid; i < 32*NL; i += 256)
        x_s[i] = x[(size_t)n0*NL + i];
    for (int i = tid; i < 2*16*HLD; i += 256)
        h_s[i] = __float2half(0.0f);
    __syncthreads();
    if (tid < 32){
        h_s[tid*HLD + 128] = __float2half(1.0f);
        h_s[tid*HLD + 129] = __float2half(x_s[tid*NL]);
    }

    // load pre-swizzled weight fragments (144 regs, stationary for 192 steps)
    uint2 fbw[9][8];
    {
        const uint2* WB = d_WB + (size_t)(ht*8 + wid)*9*8*32;
        #pragma unroll
        for (int kt = 0; kt < 9; kt++)
            #pragma unroll
            for (int j = 0; j < 8; j++)
                fbw[kt][j] = WB[(kt*8 + j)*32 + lane];
    }

    float cA[2][4], cB[2][4];
    #pragma unroll
    for (int rs = 0; rs < 2; rs++)
        #pragma unroll
        for (int m = 0; m < 4; m++){ cA[rs][m] = 0.0f; cB[rs][m] = 0.0f; }

    const uint32_t hsm = (uint32_t)__cvta_generic_to_shared(h_s);
    const uint32_t aoff = ((lane & 15)*HLD + ((lane >> 4) << 3)) * 2;
    const uint32_t abaseA = hsm + aoff;
    const uint32_t abaseB = hsm + 16*HLD*2 + aoff;

    float accA[8][4], accB[8][4];
    __syncthreads();

    #pragma unroll 1
    for (int t = 0; t < NL; t++){
        // phase 1: MMA group A at t; elementwise group B finishing step t-1
        mma_group(abaseA, fbw, accA);
        if (t > 0) ew_step(accB, cB, h_s + 16*HLD, x_s, 16, t-1, wid, lane);
        __syncthreads();
        // phase 2: MMA group B at t; elementwise group A at t
        mma_group(abaseB, fbw, accB);
        ew_step(accA, cA, h_s, x_s, 0, t, wid, lane);
        __syncthreads();
    }
    ew_step(accB, cB, h_s + 16*HLD, x_s, 16, NL-1, wid, lane);
    __syncthreads();

    // write final hidden as q/k vectors (rows 0..31 contiguous in h_s)
    for (int i = tid; i < 32*ND; i += 256){
        int m = i >> 7, u = i & 127;
        d_QK[((size_t)ht*NPAD_QK + n0 + m)*ND + u] = h_s[m*HLD + u];
    }
}

// ---------------- v LSTM (hidden size 1, scalar recurrence) ----------------
__global__ void lstm_v(const float* __restrict__ x,
                       const float* __restrict__ vWih, const float* __restrict__ vWhh,
                       const float* __restrict__ vbih, const float* __restrict__ vbhh){
    int g = blockIdx.x * blockDim.x + threadIdx.x;
    if (g >= NH * NN) return;
    int h = g / NN, n = g % NN;
    float wii = vWih[h*4+0], wif = vWih[h*4+1], wig = vWih[h*4+2], wio = vWih[h*4+3];
    float whi = vWhh[h*4+0], whf = vWhh[h*4+1], whg = vWhh[h*4+2], who = vWhh[h*4+3];
    float bi = vbih[h*4+0] + vbhh[h*4+0];
    float bf = vbih[h*4+1] + vbhh[h*4+1];
    float bg = vbih[h*4+2] + vbhh[h*4+2];
    float bo = vbih[h*4+3] + vbhh[h*4+3];
    const float* xr = x + (size_t)n*NL;
    __half* vout = d_V + ((size_t)h*NPAD_V + n)*NL;
    float hh = 0.0f, c = 0.0f;
    for (int t = 0; t < NL; t++){
        float xv = xr[t];
        float zi = fmaf(xv, wii, fmaf(hh, whi, bi));
        float zf = fmaf(xv, wif, fmaf(hh, whf, bf));
        float zg = fmaf(xv, wig, fmaf(hh, whg, bg));
        float zo = fmaf(xv, wio, fmaf(hh, who, bo));
        c = fmaf(fsig(zf), c, fsig(zi) * ftanh(zg));
        hh = fsig(zo) * ftanh(c);
        vout[t] = __float2half(hh);
    }
}

// ---------------- attention: per (h, b, 64-row q-tile) ----------------
__global__ void __launch_bounds__(256, 1) attn_kernel(float* __restrict__ out){
    const int qt = blockIdx.x;   // 0..5
    const int b  = blockIdx.y;   // 0..31
    const int h  = blockIdx.z;   // 0..7
    extern __shared__ char smem[];
    float*  sc = (float*)smem;                                   // [64][344] fp32 scores
    __half* pa = (__half*)(smem + 64*MLDM*4);                    // [64][344] fp16 probs (unnormalized)
    float*  os = (float*)(smem + 64*MLDM*4 + 64*MLDM*2);         // [64][200] fp32 out staging
    float*  rs = (float*)(smem + 64*MLDM*4 + 64*MLDM*2 + 64*200*4); // [64] reciprocal row sums
    const int tid = threadIdx.x, wid = tid >> 5;
    const int s0 = qt * 64;
    const __half* Q = d_QK + ((size_t)h*NPAD_QK      + b*NS + s0) * ND;
    const __half* K = d_QK + ((size_t)(8+h)*NPAD_QK  + b*NS) * ND;
    const __half* V = d_V  + ((size_t)h*NPAD_V       + b*NS) * NL;

    // phase 1: scores = Q K^T
    for (int nt = wid; nt < 21; nt += 8){
        wmma::fragment<wmma::accumulator, 16, 16, 16, float> acc[4];
        #pragma unroll
        for (int mt = 0; mt < 4; mt++) wmma::fill_fragment(acc[mt], 0.0f);
        #pragma unroll
        for (int kt = 0; kt < 8; kt++){
            wmma::fragment<wmma::matrix_b, 16, 16, 16, __half, wmma::col_major> fbk;
            wmma::load_matrix_sync(fbk, K + nt*16*ND + kt*16, ND);
            #pragma unroll
            for (int mt = 0; mt < 4; mt++){
                wmma::fragment<wmma::matrix_a, 16, 16, 16, __half, wmma::row_major> fa;
                wmma::load_matrix_sync(fa, Q + mt*16*ND + kt*16, ND);
                wmma::mma_sync(acc[mt], fa, fbk, acc[mt]);
            }
        }
        #pragma unroll
        for (int mt = 0; mt < 4; mt++)
            wmma::store_matrix_sync(sc + mt*16*MLDM + nt*16, acc[mt], MLDM, wmma::mem_row_major);
    }
    __syncthreads();

    // phase 2: scale, leaky, mask, softmax (4 threads per row)
    {
        const int r  = tid >> 2;
        const int q4 = tid & 3;
        const float* mrow = d_mask + (s0 + r) * MLDM;
        float* srow = sc + r * MLDM;
        const float scale = 0.08838834764831845f; // 1/sqrt(128)
        float mx = -3.4e38f;
        for (int t = q4; t < TPAD; t += 4){
            float v = srow[t] * scale;
            v = (v >= 0.0f) ? v : 0.2f * v;
            v += mrow[t];
            srow[t] = v;
            mx = fmaxf(mx, v);
        }
        mx = fmaxf(mx, __shfl_xor_sync(0xffffffffu, mx, 1));
        mx = fmaxf(mx, __shfl_xor_sync(0xffffffffu, mx, 2));
        float sum = 0.0f;
        __half* prow = pa + r * MLDM;
        for (int t = q4; t < TPAD; t += 4){
            float e = fast_exp(srow[t] - mx);
            sum += e;
            prow[t] = __float2half(e);
        }
        sum += __shfl_xor_sync(0xffffffffu, sum, 1);
        sum += __shfl_xor_sync(0xffffffffu, sum, 2);
        if (q4 == 0) rs[r] = 1.0f / sum;
    }
    __syncthreads();

    // phase 3: out = probs @ V
    for (int nt = wid; nt < 12; nt += 8){
        wmma::fragment<wmma::accumulator, 16, 16, 16, float> acc[4];
        #pragma unroll
        for (int mt = 0; mt < 4; mt++) wmma::fill_fragment(acc[mt], 0.0f);
        for (int kt = 0; kt < 21; kt++){
            wmma::fragment<wmma::matrix_b, 16, 16, 16, __half, wmma::row_major> fbv;
            wmma::load_matrix_sync(fbv, V + kt*16*NL + nt*16, NL);
            #pragma unroll
            for (int mt = 0; mt < 4; mt++){
                wmma::fragment<wmma::matrix_a, 16, 16, 16, __half, wmma::row_major> fa;
                wmma::load_matrix_sync(fa, pa + mt*16*MLDM + kt*16, MLDM);
                wmma::mma_sync(acc[mt], fa, fbv, acc[mt]);
            }
        }
        #pragma unroll
        for (int mt = 0; mt < 4; mt++)
            wmma::store_matrix_sync(os + mt*16*200 + nt*16, acc[mt], 200, wmma::mem_row_major);
    }
    __syncthreads();

    // epilogue: normalize, leaky, scatter to [B,S,L,H]
    for (int i = tid; i < 64*NL; i += 256){
        int m = i / NL, l = i % NL;
        int s = s0 + m;
        if (s < NS){
            float v = os[m*200 + l] * rs[m];
            v = (v >= 0.0f) ? v : 0.2f * v;
            out[(((size_t)b*NS + s)*NL + l)*NH + h] = v;
        }
    }
}

// ---------------- launch ----------------
extern "C" void kernel_launch(void* const* d_in, const int* in_sizes, int n_in,
                              void* d_out, int out_size){
    const float* x     = (const float*)d_in[0];
    const float* graph = (const float*)d_in[1];
    const float* qWih  = (const float*)d_in[2];
    const float* qWhh  = (const float*)d_in[3];
    const float* qbih  = (const float*)d_in[4];
    const float* qbhh  = (const float*)d_in[5];
    const float* kWih  = (const float*)d_in[6];
    const float* kWhh  = (const float*)d_in[7];
    const float* kbih  = (const float*)d_in[8];
    const float* kbhh  = (const float*)d_in[9];
    const float* vWih  = (const float*)d_in[10];
    const float* vWhh  = (const float*)d_in[11];
    const float* vbih  = (const float*)d_in[12];
    const float* vbhh  = (const float*)d_in[13];
    float* out = (float*)d_out;

    const int lstm_smem = 2*16*HLD*2 + 32*NL*4;                                 // 34304
    const int attn_smem = 64*MLDM*4 + 64*MLDM*2 + 64*200*4 + 64*4;              // 183808
    cudaFuncSetAttribute(lstm_qk,     cudaFuncAttributeMaxDynamicSharedMemorySize, lstm_smem);
    cudaFuncSetAttribute(attn_kernel, cudaFuncAttributeMaxDynamicSharedMemorySize, attn_smem);

    prep_wb<<<(WB_TOT + 255)/256, 256>>>(qWih, qWhh, qbih, qbhh, kWih, kWhh, kbih, kbhh);
    prep_mask<<<(MROWS*MLDM + 255)/256, 256>>>(graph);
    zero_pads<<<(NHT*(NPAD_QK-NN)*ND + 255)/256, 256>>>();

    lstm_qk<<<dim3(NN/32, NHT), 256, lstm_smem>>>(x);
    lstm_v<<<(NH*NN + 255)/256, 256>>>(x, vWih, vWhh, vbih, vbhh);
    attn_kernel<<<dim3(6, NB, NH), 256, attn_smem>>>(out);
}